// round 2
// baseline (speedup 1.0000x reference)
#include <cuda_runtime.h>
#include <cstdint>
#include <cstddef>

#define NPTS 4096
#define BATCH 4
#define C1 512
#define H1 864
#define H2 1728
#define KNN 5

// ---------------- scratch (device globals; no runtime allocation) ----------
__device__ __align__(16) float g_D[(size_t)BATCH * NPTS * NPTS];          // 256 MB
__device__ __align__(16) float g_PQ[(size_t)BATCH * NPTS * 2 * H2];       // 226 MB
__device__ __align__(16) float g_X1[(size_t)BATCH * NPTS * H1];           // 56 MB
__device__ __align__(16) float g_Wcat[(size_t)H1 * 2 * H2];               // 12 MB
__device__ float g_sq[BATCH * NPTS];
__device__ int   g_idx[BATCH * NPTS * KNN];

// ---------------- row squared-norms: sum of fp32-rounded squares, double acc
__global__ void rowsq_kernel(const float* __restrict__ X, float* __restrict__ sq, int Cdim) {
    int b = blockIdx.y, n = blockIdx.x;
    const float* x = X + ((size_t)b * NPTS + n) * Cdim;
    double s = 0.0;
    for (int c = threadIdx.x; c < Cdim; c += 128) {
        float v = x[c];
        float p = v * v;            // ref computes x*x in fp32 first
        s += (double)p;
    }
    for (int off = 16; off; off >>= 1) s += __shfl_down_sync(0xffffffffu, s, off);
    __shared__ double red[4];
    if ((threadIdx.x & 31) == 0) red[threadIdx.x >> 5] = s;
    __syncthreads();
    if (threadIdx.x == 0) sq[b * NPTS + n] = (float)(red[0] + red[1] + red[2] + red[3]);
}

// ---------------- build Wcat = [Wa^T | (Wb-Wa)^T]  (Cin x 2*OUT) ------------
__global__ void transcat_kernel(const float* __restrict__ W, float* __restrict__ Wcat,
                                int Cin, int OUT) {
    int total = Cin * 2 * OUT;
    for (int t = blockIdx.x * blockDim.x + threadIdx.x; t < total; t += gridDim.x * blockDim.x) {
        int c = t / (2 * OUT);
        int j = t - c * (2 * OUT);
        float v;
        if (j < OUT) {
            v = W[(size_t)j * (2 * Cin) + c];
        } else {
            int o = j - OUT;
            v = W[(size_t)o * (2 * Cin) + Cin + c] - W[(size_t)o * (2 * Cin) + c];
        }
        Wcat[t] = v;
    }
}

// ---------------- SGEMM tiles ----------------------------------------------
#define BM 128
#define BN 64
#define BKD 32
#define TM 8
#define TN 4

// D[n][m] = -((sq[n]+sq[m]) - 2*G[n][m]) with G accumulated near-exactly.
// Symmetric: lower-triangle tiles only, mirror-write.
__global__ __launch_bounds__(256) void sgemm_dist_kernel(
    const float* __restrict__ X, const float* __restrict__ sq,
    float* __restrict__ D, int Cdim) {
    int b = blockIdx.z;
    int br = blockIdx.y, bc = blockIdx.x;
    if (bc > 2 * br + 1) return;   // tile fully above diagonal -> mirrored elsewhere
    const float* Xb = X + (size_t)b * NPTS * Cdim;
    float* Db = D + (size_t)b * NPTS * NPTS;
    const float* sqb = sq + b * NPTS;

    __shared__ float As[BKD][BM];
    __shared__ float Bs[BKD][BN];
    int tid = threadIdx.x;
    int tx = tid & 15, ty = tid >> 4;
    double accd[TM][TN];
    float accf[TM][TN];
#pragma unroll
    for (int i = 0; i < TM; i++)
#pragma unroll
        for (int j = 0; j < TN; j++) { accd[i][j] = 0.0; accf[i][j] = 0.f; }

    int rowA = br * BM, rowB = bc * BN;
    int arow = tid >> 1, ac = (tid & 1) * 16;
    int brow = tid >> 2, bcq = (tid & 3) * 8;

    for (int k0 = 0; k0 < Cdim; k0 += BKD) {
        const float* Arow = Xb + (size_t)(rowA + arow) * Cdim + k0 + ac;
        const float* Brow = Xb + (size_t)(rowB + brow) * Cdim + k0 + bcq;
#pragma unroll
        for (int u = 0; u < 4; u++) {
            float4 a = *(const float4*)(Arow + 4 * u);
            As[ac + 4 * u + 0][arow] = a.x;
            As[ac + 4 * u + 1][arow] = a.y;
            As[ac + 4 * u + 2][arow] = a.z;
            As[ac + 4 * u + 3][arow] = a.w;
        }
#pragma unroll
        for (int u = 0; u < 2; u++) {
            float4 bb = *(const float4*)(Brow + 4 * u);
            Bs[bcq + 4 * u + 0][brow] = bb.x;
            Bs[bcq + 4 * u + 1][brow] = bb.y;
            Bs[bcq + 4 * u + 2][brow] = bb.z;
            Bs[bcq + 4 * u + 3][brow] = bb.w;
        }
        __syncthreads();
#pragma unroll
        for (int k = 0; k < BKD; k++) {
            float ra[TM], rb[TN];
#pragma unroll
            for (int i = 0; i < TM; i++) ra[i] = As[k][ty * TM + i];
#pragma unroll
            for (int j = 0; j < TN; j++) rb[j] = Bs[k][tx * TN + j];
#pragma unroll
            for (int i = 0; i < TM; i++)
#pragma unroll
                for (int j = 0; j < TN; j++) accf[i][j] = fmaf(ra[i], rb[j], accf[i][j]);
        }
        __syncthreads();
        // promote 32-wide fp32 chunk into double accumulator (near-exact total)
#pragma unroll
        for (int i = 0; i < TM; i++)
#pragma unroll
            for (int j = 0; j < TN; j++) { accd[i][j] += (double)accf[i][j]; accf[i][j] = 0.f; }
    }
#pragma unroll
    for (int i = 0; i < TM; i++) {
        int n = rowA + ty * TM + i;
        float sn = sqb[n];
#pragma unroll
        for (int j = 0; j < TN; j++) {
            int m = rowB + tx * TN + j;
            float Gf = (float)accd[i][j];          // correctly-rounded fp32 G
            float t1 = __fadd_rn(sn, sqb[m]);      // ref: sq_n + sq_m
            float v = -__fadd_rn(t1, -__fmul_rn(2.0f, Gf));  // ref: -(t1 - 2G)
            Db[(size_t)n * NPTS + m] = v;
            if (m < n) Db[(size_t)m * NPTS + n] = v;
        }
    }
}

// PQ[n][j] = sum_c X[n][c] * Wcat[c][j]    (J = 2*OUT: [P | Q]), double-chunk acc
__global__ __launch_bounds__(256) void sgemm_pq_kernel(
    const float* __restrict__ X, const float* __restrict__ Wc,
    float* __restrict__ PQ, int Cdim, int J) {
    int b = blockIdx.z;
    int br = blockIdx.y, bc = blockIdx.x;
    const float* Xb = X + (size_t)b * NPTS * Cdim;
    float* Pb = PQ + (size_t)b * NPTS * J;

    __shared__ float As[BKD][BM];
    __shared__ float Bs[BKD][BN];
    int tid = threadIdx.x;
    int tx = tid & 15, ty = tid >> 4;
    double accd[TM][TN];
    float accf[TM][TN];
#pragma unroll
    for (int i = 0; i < TM; i++)
#pragma unroll
        for (int j = 0; j < TN; j++) { accd[i][j] = 0.0; accf[i][j] = 0.f; }

    int rowA = br * BM;
    int arow = tid >> 1, ac = (tid & 1) * 16;
    int bk = tid >> 3, bj = (tid & 7) * 8;

    for (int k0 = 0; k0 < Cdim; k0 += BKD) {
        const float* Arow = Xb + (size_t)(rowA + arow) * Cdim + k0 + ac;
        const float* Wrow = Wc + (size_t)(k0 + bk) * J + bc * BN + bj;
#pragma unroll
        for (int u = 0; u < 4; u++) {
            float4 a = *(const float4*)(Arow + 4 * u);
            As[ac + 4 * u + 0][arow] = a.x;
            As[ac + 4 * u + 1][arow] = a.y;
            As[ac + 4 * u + 2][arow] = a.z;
            As[ac + 4 * u + 3][arow] = a.w;
        }
        *(float4*)&Bs[bk][bj] = *(const float4*)(Wrow);
        *(float4*)&Bs[bk][bj + 4] = *(const float4*)(Wrow + 4);
        __syncthreads();
#pragma unroll
        for (int k = 0; k < BKD; k++) {
            float ra[TM], rb[TN];
#pragma unroll
            for (int i = 0; i < TM; i++) ra[i] = As[k][ty * TM + i];
#pragma unroll
            for (int j = 0; j < TN; j++) rb[j] = Bs[k][tx * TN + j];
#pragma unroll
            for (int i = 0; i < TM; i++)
#pragma unroll
                for (int j = 0; j < TN; j++) accf[i][j] = fmaf(ra[i], rb[j], accf[i][j]);
        }
        __syncthreads();
#pragma unroll
        for (int i = 0; i < TM; i++)
#pragma unroll
            for (int j = 0; j < TN; j++) { accd[i][j] += (double)accf[i][j]; accf[i][j] = 0.f; }
    }
#pragma unroll
    for (int i = 0; i < TM; i++) {
        int n = rowA + ty * TM + i;
#pragma unroll
        for (int j = 0; j < TN; j++) {
            Pb[(size_t)n * J + bc * BN + tx * TN + j] = (float)accd[i][j];
        }
    }
}

// ---------------- top-5 (largest) per row of D; tie-break = lower index -----
__global__ void topk5_kernel(const float* __restrict__ D, int* __restrict__ idx) {
    int b = blockIdx.y, n = blockIdx.x;
    const float* row = D + ((size_t)b * NPTS + n) * NPTS;
    float tv[KNN];
    int   ti[KNN];
#pragma unroll
    for (int j = 0; j < KNN; j++) { tv[j] = -__int_as_float(0x7f800000); ti[j] = 0x7fffffff; }
    for (int m = threadIdx.x; m < NPTS; m += 128) {
        float v = row[m];
        if (v > tv[KNN - 1]) {
            int j = KNN - 1;
            while (j > 0 && v > tv[j - 1]) { tv[j] = tv[j - 1]; ti[j] = ti[j - 1]; j--; }
            tv[j] = v; ti[j] = m;
        }
    }
    __shared__ float sv[128];
    __shared__ int   si[128];
    __shared__ int   swin;
    int head = 0;
    for (int p = 0; p < KNN; p++) {
        sv[threadIdx.x] = (head < KNN) ? tv[head] : -__int_as_float(0x7f800000);
        si[threadIdx.x] = (head < KNN) ? ti[head] : 0x7fffffff;
        __syncthreads();
        if (threadIdx.x < 32) {
            float bv = -__int_as_float(0x7f800000);
            int bi = 0x7fffffff, bt = -1;
            for (int t = threadIdx.x; t < 128; t += 32) {
                float v = sv[t]; int i2 = si[t];
                if (v > bv || (v == bv && i2 < bi)) { bv = v; bi = i2; bt = t; }
            }
            for (int off = 16; off; off >>= 1) {
                float ov = __shfl_down_sync(0xffffffffu, bv, off);
                int oi = __shfl_down_sync(0xffffffffu, bi, off);
                int ot = __shfl_down_sync(0xffffffffu, bt, off);
                if (ov > bv || (ov == bv && oi < bi)) { bv = ov; bi = oi; bt = ot; }
            }
            if (threadIdx.x == 0) {
                idx[((size_t)b * NPTS + n) * KNN + p] = bi;
                swin = bt;
            }
        }
        __syncthreads();
        if (threadIdx.x == swin) head++;
        __syncthreads();
    }
}

// ---------------- gather + max over k + BN + LeakyReLU (double epilogue) ----
__global__ void gathermax_kernel(const float* __restrict__ PQ, const int* __restrict__ idx,
                                 const float* __restrict__ gamma, const float* __restrict__ beta,
                                 const float* __restrict__ mean, const float* __restrict__ var,
                                 float* __restrict__ out, int OUT) {
    int b = blockIdx.y, n = blockIdx.x;
    __shared__ int nb[KNN];
    if (threadIdx.x < KNN) nb[threadIdx.x] = idx[((size_t)b * NPTS + n) * KNN + threadIdx.x];
    __syncthreads();
    int J = 2 * OUT;
    const float* base = PQ + (size_t)b * NPTS * J;
    const float* p0 = base + (size_t)nb[0] * J;
    const float* p1 = base + (size_t)nb[1] * J;
    const float* p2 = base + (size_t)nb[2] * J;
    const float* p3 = base + (size_t)nb[3] * J;
    const float* p4 = base + (size_t)nb[4] * J;
    const float* q  = base + (size_t)n * J + OUT;
    float* orow = out + ((size_t)b * NPTS + n) * OUT;
    for (int o = threadIdx.x; o < OUT; o += blockDim.x) {
        float m = p0[o];
        m = fmaxf(m, p1[o]);
        m = fmaxf(m, p2[o]);
        m = fmaxf(m, p3[o]);
        m = fmaxf(m, p4[o]);
        double h = (double)m + (double)q[o];
        double s = (double)gamma[o] * rsqrt((double)var[o] + 1e-5);
        double v = ((double)h - (double)mean[o]) * s + (double)beta[o];
        float vf = (float)v;
        orow[o] = (vf >= 0.f) ? vf : 0.2f * vf;
    }
}

// ---------------- launcher ---------------------------------------------------
extern "C" void kernel_launch(void* const* d_in, const int* in_sizes, int n_in,
                              void* d_out, int out_size) {
    const float* X0 = (const float*)d_in[0];
    const float* W1 = (const float*)d_in[1];
    const float* g1 = (const float*)d_in[2];
    const float* b1 = (const float*)d_in[3];
    const float* m1 = (const float*)d_in[4];
    const float* v1 = (const float*)d_in[5];
    const float* W2 = (const float*)d_in[6];
    const float* g2 = (const float*)d_in[7];
    const float* b2 = (const float*)d_in[8];
    const float* m2 = (const float*)d_in[9];
    const float* v2 = (const float*)d_in[10];
    float* out = (float*)d_out;

    float *pD, *pPQ, *pX1, *pWc, *pSq;
    int* pIdx;
    cudaGetSymbolAddress((void**)&pD, g_D);
    cudaGetSymbolAddress((void**)&pPQ, g_PQ);
    cudaGetSymbolAddress((void**)&pX1, g_X1);
    cudaGetSymbolAddress((void**)&pWc, g_Wcat);
    cudaGetSymbolAddress((void**)&pSq, g_sq);
    cudaGetSymbolAddress((void**)&pIdx, g_idx);

    // ---- Block 1: Cin=512, OUT=864 ----
    rowsq_kernel<<<dim3(NPTS, BATCH), 128>>>(X0, pSq, C1);
    transcat_kernel<<<256, 256>>>(W1, pWc, C1, H1);
    sgemm_dist_kernel<<<dim3(NPTS / BN, NPTS / BM, BATCH), 256>>>(X0, pSq, pD, C1);
    topk5_kernel<<<dim3(NPTS, BATCH), 128>>>(pD, pIdx);
    sgemm_pq_kernel<<<dim3(2 * H1 / BN, NPTS / BM, BATCH), 256>>>(X0, pWc, pPQ, C1, 2 * H1);
    gathermax_kernel<<<dim3(NPTS, BATCH), 256>>>(pPQ, pIdx, g1, b1, m1, v1, pX1, H1);

    // ---- Block 2: Cin=864, OUT=1728 ----
    rowsq_kernel<<<dim3(NPTS, BATCH), 128>>>(pX1, pSq, H1);
    transcat_kernel<<<512, 256>>>(W2, pWc, H1, H2);
    sgemm_dist_kernel<<<dim3(NPTS / BN, NPTS / BM, BATCH), 256>>>(pX1, pSq, pD, H1);
    topk5_kernel<<<dim3(NPTS, BATCH), 128>>>(pD, pIdx);
    sgemm_pq_kernel<<<dim3(2 * H2 / BN, NPTS / BM, BATCH), 256>>>(pX1, pWc, pPQ, H1, 2 * H2);
    gathermax_kernel<<<dim3(NPTS, BATCH), 256>>>(pPQ, pIdx, g2, b2, m2, v2, out, H2);
}

// round 3
// speedup vs baseline: 1.0004x; 1.0004x over previous
#include <cuda_runtime.h>
#include <cstdint>
#include <cstddef>

#define NPTS 4096
#define BATCH 4
#define C1 512
#define H1 864
#define H2 1728
#define KNN 5

// ---------------- scratch (device globals; no runtime allocation) ----------
__device__ __align__(16) float g_D[(size_t)BATCH * NPTS * NPTS];          // 256 MB
__device__ __align__(16) float g_PQ[(size_t)BATCH * NPTS * 2 * H2];       // 226 MB
__device__ __align__(16) float g_X1[(size_t)BATCH * NPTS * H1];           // 56 MB
__device__ __align__(16) float g_Wcat[(size_t)H1 * 2 * H2];               // 12 MB
__device__ float g_sq[BATCH * NPTS];
__device__ int   g_idx[BATCH * NPTS * KNN];

// ---------------- row squared-norms: sum of fp32-rounded squares, double acc
__global__ void rowsq_kernel(const float* __restrict__ X, float* __restrict__ sq, int Cdim) {
    int b = blockIdx.y, n = blockIdx.x;
    const float* x = X + ((size_t)b * NPTS + n) * Cdim;
    double s = 0.0;
    for (int c = threadIdx.x; c < Cdim; c += 128) {
        float v = x[c];
        float p = v * v;            // ref computes x*x in fp32 first
        s += (double)p;
    }
    for (int off = 16; off; off >>= 1) s += __shfl_down_sync(0xffffffffu, s, off);
    __shared__ double red[4];
    if ((threadIdx.x & 31) == 0) red[threadIdx.x >> 5] = s;
    __syncthreads();
    if (threadIdx.x == 0) sq[b * NPTS + n] = (float)(red[0] + red[1] + red[2] + red[3]);
}

// ---------------- build Wcat = [Wa^T | (Wb-Wa)^T]  (Cin x 2*OUT) ------------
__global__ void transcat_kernel(const float* __restrict__ W, float* __restrict__ Wcat,
                                int Cin, int OUT) {
    int total = Cin * 2 * OUT;
    for (int t = blockIdx.x * blockDim.x + threadIdx.x; t < total; t += gridDim.x * blockDim.x) {
        int c = t / (2 * OUT);
        int j = t - c * (2 * OUT);
        float v;
        if (j < OUT) {
            v = W[(size_t)j * (2 * Cin) + c];
        } else {
            int o = j - OUT;
            v = W[(size_t)o * (2 * Cin) + Cin + c] - W[(size_t)o * (2 * Cin) + c];
        }
        Wcat[t] = v;
    }
}

// ---------------- SGEMM tiles ----------------------------------------------
#define BM 128
#define BN 64
#define BKD 32
#define TM 8
#define TN 4

// D[n][m] = -((sq[n]+sq[m]) - 2*G[n][m]) with G accumulated near-exactly.
// Symmetric: lower-triangle tiles only, mirror-write.
__global__ __launch_bounds__(256) void sgemm_dist_kernel(
    const float* __restrict__ X, const float* __restrict__ sq,
    float* __restrict__ D, int Cdim) {
    int b = blockIdx.z;
    int br = blockIdx.y, bc = blockIdx.x;
    if (bc > 2 * br + 1) return;   // tile fully above diagonal -> mirrored elsewhere
    const float* Xb = X + (size_t)b * NPTS * Cdim;
    float* Db = D + (size_t)b * NPTS * NPTS;
    const float* sqb = sq + b * NPTS;

    __shared__ float As[BKD][BM];
    __shared__ float Bs[BKD][BN];
    int tid = threadIdx.x;
    int tx = tid & 15, ty = tid >> 4;
    double accd[TM][TN];
    float accf[TM][TN];
#pragma unroll
    for (int i = 0; i < TM; i++)
#pragma unroll
        for (int j = 0; j < TN; j++) { accd[i][j] = 0.0; accf[i][j] = 0.f; }

    int rowA = br * BM, rowB = bc * BN;
    int arow = tid >> 1, ac = (tid & 1) * 16;
    int brow = tid >> 2, bcq = (tid & 3) * 8;

    for (int k0 = 0; k0 < Cdim; k0 += BKD) {
        const float* Arow = Xb + (size_t)(rowA + arow) * Cdim + k0 + ac;
        const float* Brow = Xb + (size_t)(rowB + brow) * Cdim + k0 + bcq;
#pragma unroll
        for (int u = 0; u < 4; u++) {
            float4 a = *(const float4*)(Arow + 4 * u);
            As[ac + 4 * u + 0][arow] = a.x;
            As[ac + 4 * u + 1][arow] = a.y;
            As[ac + 4 * u + 2][arow] = a.z;
            As[ac + 4 * u + 3][arow] = a.w;
        }
#pragma unroll
        for (int u = 0; u < 2; u++) {
            float4 bb = *(const float4*)(Brow + 4 * u);
            Bs[bcq + 4 * u + 0][brow] = bb.x;
            Bs[bcq + 4 * u + 1][brow] = bb.y;
            Bs[bcq + 4 * u + 2][brow] = bb.z;
            Bs[bcq + 4 * u + 3][brow] = bb.w;
        }
        __syncthreads();
#pragma unroll
        for (int k = 0; k < BKD; k++) {
            float ra[TM], rb[TN];
#pragma unroll
            for (int i = 0; i < TM; i++) ra[i] = As[k][ty * TM + i];
#pragma unroll
            for (int j = 0; j < TN; j++) rb[j] = Bs[k][tx * TN + j];
#pragma unroll
            for (int i = 0; i < TM; i++)
#pragma unroll
                for (int j = 0; j < TN; j++) accf[i][j] = fmaf(ra[i], rb[j], accf[i][j]);
        }
        __syncthreads();
        // promote 32-wide fp32 chunk into double accumulator (near-exact total)
#pragma unroll
        for (int i = 0; i < TM; i++)
#pragma unroll
            for (int j = 0; j < TN; j++) { accd[i][j] += (double)accf[i][j]; accf[i][j] = 0.f; }
    }
#pragma unroll
    for (int i = 0; i < TM; i++) {
        int n = rowA + ty * TM + i;
        float sn = sqb[n];
#pragma unroll
        for (int j = 0; j < TN; j++) {
            int m = rowB + tx * TN + j;
            float Gf = (float)accd[i][j];          // correctly-rounded fp32 G
            float t1 = __fadd_rn(sn, sqb[m]);      // ref: sq_n + sq_m
            float v = -__fadd_rn(t1, -__fmul_rn(2.0f, Gf));  // ref: -(t1 - 2G)
            Db[(size_t)n * NPTS + m] = v;
            if (m < n) Db[(size_t)m * NPTS + n] = v;
        }
    }
}

// PQ[n][j] = sum_c X[n][c] * Wcat[c][j]    (J = 2*OUT: [P | Q]), double-chunk acc
__global__ __launch_bounds__(256) void sgemm_pq_kernel(
    const float* __restrict__ X, const float* __restrict__ Wc,
    float* __restrict__ PQ, int Cdim, int J) {
    int b = blockIdx.z;
    int br = blockIdx.y, bc = blockIdx.x;
    const float* Xb = X + (size_t)b * NPTS * Cdim;
    float* Pb = PQ + (size_t)b * NPTS * J;

    __shared__ float As[BKD][BM];
    __shared__ float Bs[BKD][BN];
    int tid = threadIdx.x;
    int tx = tid & 15, ty = tid >> 4;
    double accd[TM][TN];
    float accf[TM][TN];
#pragma unroll
    for (int i = 0; i < TM; i++)
#pragma unroll
        for (int j = 0; j < TN; j++) { accd[i][j] = 0.0; accf[i][j] = 0.f; }

    int rowA = br * BM;
    int arow = tid >> 1, ac = (tid & 1) * 16;
    int bk = tid >> 3, bj = (tid & 7) * 8;

    for (int k0 = 0; k0 < Cdim; k0 += BKD) {
        const float* Arow = Xb + (size_t)(rowA + arow) * Cdim + k0 + ac;
        const float* Wrow = Wc + (size_t)(k0 + bk) * J + bc * BN + bj;
#pragma unroll
        for (int u = 0; u < 4; u++) {
            float4 a = *(const float4*)(Arow + 4 * u);
            As[ac + 4 * u + 0][arow] = a.x;
            As[ac + 4 * u + 1][arow] = a.y;
            As[ac + 4 * u + 2][arow] = a.z;
            As[ac + 4 * u + 3][arow] = a.w;
        }
        *(float4*)&Bs[bk][bj] = *(const float4*)(Wrow);
        *(float4*)&Bs[bk][bj + 4] = *(const float4*)(Wrow + 4);
        __syncthreads();
#pragma unroll
        for (int k = 0; k < BKD; k++) {
            float ra[TM], rb[TN];
#pragma unroll
            for (int i = 0; i < TM; i++) ra[i] = As[k][ty * TM + i];
#pragma unroll
            for (int j = 0; j < TN; j++) rb[j] = Bs[k][tx * TN + j];
#pragma unroll
            for (int i = 0; i < TM; i++)
#pragma unroll
                for (int j = 0; j < TN; j++) accf[i][j] = fmaf(ra[i], rb[j], accf[i][j]);
        }
        __syncthreads();
#pragma unroll
        for (int i = 0; i < TM; i++)
#pragma unroll
            for (int j = 0; j < TN; j++) { accd[i][j] += (double)accf[i][j]; accf[i][j] = 0.f; }
    }
#pragma unroll
    for (int i = 0; i < TM; i++) {
        int n = rowA + ty * TM + i;
#pragma unroll
        for (int j = 0; j < TN; j++) {
            Pb[(size_t)n * J + bc * BN + tx * TN + j] = (float)accd[i][j];
        }
    }
}

// ---------------- top-5 (largest) per row of D; tie-break = lower index -----
__global__ void topk5_kernel(const float* __restrict__ D, int* __restrict__ idx) {
    int b = blockIdx.y, n = blockIdx.x;
    const float* row = D + ((size_t)b * NPTS + n) * NPTS;
    float tv[KNN];
    int   ti[KNN];
#pragma unroll
    for (int j = 0; j < KNN; j++) { tv[j] = -__int_as_float(0x7f800000); ti[j] = 0x7fffffff; }
    for (int m = threadIdx.x; m < NPTS; m += 128) {
        float v = row[m];
        if (v > tv[KNN - 1]) {
            int j = KNN - 1;
            while (j > 0 && v > tv[j - 1]) { tv[j] = tv[j - 1]; ti[j] = ti[j - 1]; j--; }
            tv[j] = v; ti[j] = m;
        }
    }
    __shared__ float sv[128];
    __shared__ int   si[128];
    __shared__ int   swin;
    int head = 0;
    for (int p = 0; p < KNN; p++) {
        sv[threadIdx.x] = (head < KNN) ? tv[head] : -__int_as_float(0x7f800000);
        si[threadIdx.x] = (head < KNN) ? ti[head] : 0x7fffffff;
        __syncthreads();
        if (threadIdx.x < 32) {
            float bv = -__int_as_float(0x7f800000);
            int bi = 0x7fffffff, bt = -1;
            for (int t = threadIdx.x; t < 128; t += 32) {
                float v = sv[t]; int i2 = si[t];
                if (v > bv || (v == bv && i2 < bi)) { bv = v; bi = i2; bt = t; }
            }
            for (int off = 16; off; off >>= 1) {
                float ov = __shfl_down_sync(0xffffffffu, bv, off);
                int oi = __shfl_down_sync(0xffffffffu, bi, off);
                int ot = __shfl_down_sync(0xffffffffu, bt, off);
                if (ov > bv || (ov == bv && oi < bi)) { bv = ov; bi = oi; bt = ot; }
            }
            if (threadIdx.x == 0) {
                idx[((size_t)b * NPTS + n) * KNN + p] = bi;
                swin = bt;
            }
        }
        __syncthreads();
        if (threadIdx.x == swin) head++;
        __syncthreads();
    }
}

// ---------------- gather + max over k + BN + LeakyReLU (double epilogue) ----
__global__ void gathermax_kernel(const float* __restrict__ PQ, const int* __restrict__ idx,
                                 const float* __restrict__ gamma, const float* __restrict__ beta,
                                 const float* __restrict__ mean, const float* __restrict__ var,
                                 float* __restrict__ out, int OUT) {
    int b = blockIdx.y, n = blockIdx.x;
    __shared__ int nb[KNN];
    if (threadIdx.x < KNN) nb[threadIdx.x] = idx[((size_t)b * NPTS + n) * KNN + threadIdx.x];
    __syncthreads();
    int J = 2 * OUT;
    const float* base = PQ + (size_t)b * NPTS * J;
    const float* p0 = base + (size_t)nb[0] * J;
    const float* p1 = base + (size_t)nb[1] * J;
    const float* p2 = base + (size_t)nb[2] * J;
    const float* p3 = base + (size_t)nb[3] * J;
    const float* p4 = base + (size_t)nb[4] * J;
    const float* q  = base + (size_t)n * J + OUT;
    float* orow = out + ((size_t)b * NPTS + n) * OUT;
    for (int o = threadIdx.x; o < OUT; o += blockDim.x) {
        float m = p0[o];
        m = fmaxf(m, p1[o]);
        m = fmaxf(m, p2[o]);
        m = fmaxf(m, p3[o]);
        m = fmaxf(m, p4[o]);
        double h = (double)m + (double)q[o];
        double s = (double)gamma[o] * rsqrt((double)var[o] + 1e-5);
        double v = ((double)h - (double)mean[o]) * s + (double)beta[o];
        float vf = (float)v;
        orow[o] = (vf >= 0.f) ? vf : 0.2f * vf;
    }
}

// ---------------- launcher ---------------------------------------------------
extern "C" void kernel_launch(void* const* d_in, const int* in_sizes, int n_in,
                              void* d_out, int out_size) {
    const float* X0 = (const float*)d_in[0];
    const float* W1 = (const float*)d_in[1];
    const float* g1 = (const float*)d_in[2];
    const float* b1 = (const float*)d_in[3];
    const float* m1 = (const float*)d_in[4];
    const float* v1 = (const float*)d_in[5];
    const float* W2 = (const float*)d_in[6];
    const float* g2 = (const float*)d_in[7];
    const float* b2 = (const float*)d_in[8];
    const float* m2 = (const float*)d_in[9];
    const float* v2 = (const float*)d_in[10];
    float* out = (float*)d_out;

    float *pD, *pPQ, *pX1, *pWc, *pSq;
    int* pIdx;
    cudaGetSymbolAddress((void**)&pD, g_D);
    cudaGetSymbolAddress((void**)&pPQ, g_PQ);
    cudaGetSymbolAddress((void**)&pX1, g_X1);
    cudaGetSymbolAddress((void**)&pWc, g_Wcat);
    cudaGetSymbolAddress((void**)&pSq, g_sq);
    cudaGetSymbolAddress((void**)&pIdx, g_idx);

    // ---- Block 1: Cin=512, OUT=864 ----
    rowsq_kernel<<<dim3(NPTS, BATCH), 128>>>(X0, pSq, C1);
    transcat_kernel<<<256, 256>>>(W1, pWc, C1, H1);
    sgemm_dist_kernel<<<dim3(NPTS / BN, NPTS / BM, BATCH), 256>>>(X0, pSq, pD, C1);
    topk5_kernel<<<dim3(NPTS, BATCH), 128>>>(pD, pIdx);
    sgemm_pq_kernel<<<dim3(2 * H1 / BN, NPTS / BM, BATCH), 256>>>(X0, pWc, pPQ, C1, 2 * H1);
    gathermax_kernel<<<dim3(NPTS, BATCH), 256>>>(pPQ, pIdx, g1, b1, m1, v1, pX1, H1);

    // ---- Block 2: Cin=864, OUT=1728 ----
    rowsq_kernel<<<dim3(NPTS, BATCH), 128>>>(pX1, pSq, H1);
    transcat_kernel<<<512, 256>>>(W2, pWc, H1, H2);
    sgemm_dist_kernel<<<dim3(NPTS / BN, NPTS / BM, BATCH), 256>>>(pX1, pSq, pD, H1);
    topk5_kernel<<<dim3(NPTS, BATCH), 128>>>(pD, pIdx);
    sgemm_pq_kernel<<<dim3(2 * H2 / BN, NPTS / BM, BATCH), 256>>>(pX1, pWc, pPQ, H1, 2 * H2);
    gathermax_kernel<<<dim3(NPTS, BATCH), 256>>>(pPQ, pIdx, g2, b2, m2, v2, out, H2);
}

// round 5
// speedup vs baseline: 3.2346x; 3.2333x over previous
#include <cuda_runtime.h>
#include <cuda_bf16.h>
#include <cstdint>
#include <cstddef>

#define NPTS 4096
#define BATCH 4
#define C1 512
#define H1 864
#define H2 1728
#define KNN 5
#define NCAND 8
#define KP1 512
#define KP2 896
#define J1P 1792
#define J2P 3456

// GEMM tiling
#define BM 128
#define BN 128
#define BKH 32      // halves per K chunk
#define ROWH 40     // padded smem row stride (halves) -> conflict-free

// ---------------- scratch (device globals) ----------------------------------
__device__ __align__(16) float g_D[(size_t)BATCH * NPTS * NPTS];               // 256 MB
__device__ __align__(16) float g_PQ[(size_t)BATCH * NPTS * J2P];               // 226 MB
__device__ __align__(16) float g_X1[(size_t)BATCH * NPTS * H1];                // 56 MB
__device__ __align__(16) __nv_bfloat16 g_XA[(size_t)3 * BATCH * NPTS * KP2];   // 88 MB
__device__ __align__(16) __nv_bfloat16 g_WB[(size_t)3 * J2P * KP2];            // 18.6 MB
__device__ float g_sq[BATCH * NPTS];
__device__ int   g_idx[BATCH * NPTS * KNN];
__device__ int   g_cand[BATCH * NPTS * NCAND];

// ---------------- helpers ----------------------------------------------------
__device__ __forceinline__ uint32_t smem_u32(const void* p) {
    uint32_t a;
    asm("{ .reg .u64 t; cvta.to.shared.u64 t, %1; cvt.u32.u64 %0, t; }" : "=r"(a) : "l"(p));
    return a;
}
__device__ __forceinline__ void cp16(uint32_t s, const void* g) {
    asm volatile("cp.async.cg.shared.global [%0], [%1], 16;" :: "r"(s), "l"(g));
}
__device__ __forceinline__ void cp_commit() {
    asm volatile("cp.async.commit_group;" ::: "memory");
}
__device__ __forceinline__ void cp_wait1() {
    asm volatile("cp.async.wait_group 1;" ::: "memory");
}
__device__ __forceinline__ void cp_wait0() {
    asm volatile("cp.async.wait_group 0;" ::: "memory");
}
__device__ __forceinline__ void mma16816(float* c, const uint32_t* a, const uint32_t* b) {
    asm volatile(
        "mma.sync.aligned.m16n8k16.row.col.f32.bf16.bf16.f32 "
        "{%0,%1,%2,%3}, {%4,%5,%6,%7}, {%8,%9}, {%0,%1,%2,%3};"
        : "+f"(c[0]), "+f"(c[1]), "+f"(c[2]), "+f"(c[3])
        : "r"(a[0]), "r"(a[1]), "r"(a[2]), "r"(a[3]), "r"(b[0]), "r"(b[1]));
}

// ---------------- small kernels ---------------------------------------------
__global__ void rowsq_kernel(const float* __restrict__ X, float* __restrict__ sq, int Cdim) {
    int b = blockIdx.y, n = blockIdx.x;
    const float* x = X + ((size_t)b * NPTS + n) * Cdim;
    double s = 0.0;
    for (int c = threadIdx.x; c < Cdim; c += 128) { float v = x[c]; s += (double)(v * v); }
    for (int off = 16; off; off >>= 1) s += __shfl_down_sync(0xffffffffu, s, off);
    __shared__ double red[4];
    if ((threadIdx.x & 31) == 0) red[threadIdx.x >> 5] = s;
    __syncthreads();
    if (threadIdx.x == 0) sq[b * NPTS + n] = (float)(red[0] + red[1] + red[2] + red[3]);
}

__global__ void split3x_kernel(const float* __restrict__ X, __nv_bfloat16* __restrict__ P,
                               int Cin, int Kp, size_t planeStride) {
    size_t total = (size_t)BATCH * NPTS * Kp;
    for (size_t t = (size_t)blockIdx.x * blockDim.x + threadIdx.x; t < total;
         t += (size_t)gridDim.x * blockDim.x) {
        size_t bn = t / Kp; int c = (int)(t - bn * Kp);
        float x = (c < Cin) ? X[bn * Cin + c] : 0.f;
        __nv_bfloat16 h0 = __float2bfloat16(x);
        float r1 = x - __bfloat162float(h0);
        __nv_bfloat16 h1 = __float2bfloat16(r1);
        float r2 = r1 - __bfloat162float(h1);
        __nv_bfloat16 h2 = __float2bfloat16(r2);
        P[t] = h0; P[planeStride + t] = h1; P[2 * planeStride + t] = h2;
    }
}

__global__ void splitW_kernel(const float* __restrict__ W, __nv_bfloat16* __restrict__ P,
                              int Cin, int OUT, int Kp, size_t planeStride) {
    size_t total = (size_t)2 * OUT * Kp;
    for (size_t t = (size_t)blockIdx.x * blockDim.x + threadIdx.x; t < total;
         t += (size_t)gridDim.x * blockDim.x) {
        size_t j = t / Kp; int c = (int)(t - j * Kp);
        float w = 0.f;
        if (c < Cin) {
            if ((int)j < OUT) w = W[j * (2 * Cin) + c];
            else { size_t o = j - OUT; w = __fadd_rn(W[o * (2 * Cin) + Cin + c], -W[o * (2 * Cin) + c]); }
        }
        __nv_bfloat16 h0 = __float2bfloat16(w);
        float r1 = w - __bfloat162float(h0);
        __nv_bfloat16 h1 = __float2bfloat16(r1);
        float r2 = r1 - __bfloat162float(h1);
        __nv_bfloat16 h2 = __float2bfloat16(r2);
        P[t] = h0; P[planeStride + t] = h1; P[2 * planeStride + t] = h2;
    }
}

// ---------------- HMMA GEMM --------------------------------------------------
struct TermList { int n; int pa[3]; int pb[3]; };

// mode 0: distance D from X@X^T (triangle + mirror). mode 1: PQ = X@W^T (float out)
__global__ __launch_bounds__(256, 2) void hmma_gemm_kernel(
    const __nv_bfloat16* __restrict__ A0, const __nv_bfloat16* __restrict__ B0,
    size_t aPlane, size_t bPlane, size_t aBatch, size_t bBatch,
    int Kp, TermList tl, int mode,
    const float* __restrict__ sq, float* __restrict__ Out, int JS) {
    __shared__ __align__(16) __nv_bfloat16 smA[2][BM * ROWH];
    __shared__ __align__(16) __nv_bfloat16 smB[2][BN * ROWH];

    int tid = threadIdx.x;
    int bb = blockIdx.z;
    int br = blockIdx.y, bc = blockIdx.x;
    if (mode == 0 && bc > br) return;
    int rowA = br * BM, rowB = bc * BN;

    const __nv_bfloat16* Aptr[3];
    const __nv_bfloat16* Bptr[3];
#pragma unroll
    for (int t = 0; t < 3; t++) {
        int tt = (t < tl.n) ? t : 0;
        Aptr[t] = A0 + (size_t)tl.pa[tt] * aPlane + (size_t)bb * aBatch + (size_t)rowA * Kp;
        Bptr[t] = B0 + (size_t)tl.pb[tt] * bPlane + (size_t)bb * bBatch + (size_t)rowB * Kp;
    }

    uint32_t sA[2] = { smem_u32(smA[0]), smem_u32(smA[1]) };
    uint32_t sB[2] = { smem_u32(smB[0]), smem_u32(smB[1]) };

    // per-thread load slots: 2 vec16 for A, 2 for B
    int v0 = tid, v1 = tid + 256;
    int ra0 = v0 >> 2, ca0 = (v0 & 3) * 8;
    int ra1 = v1 >> 2, ca1 = (v1 & 3) * 8;

    int chPerTerm = Kp / BKH;
    int nch = tl.n * chPerTerm;

    // chunk 0
    {
        const __nv_bfloat16* Ag = Aptr[0];
        const __nv_bfloat16* Bg = Bptr[0];
        cp16(sA[0] + (ra0 * ROWH + ca0) * 2, Ag + (size_t)ra0 * Kp + ca0);
        cp16(sA[0] + (ra1 * ROWH + ca1) * 2, Ag + (size_t)ra1 * Kp + ca1);
        cp16(sB[0] + (ra0 * ROWH + ca0) * 2, Bg + (size_t)ra0 * Kp + ca0);
        cp16(sB[0] + (ra1 * ROWH + ca1) * 2, Bg + (size_t)ra1 * Kp + ca1);
        cp_commit();
    }

    float acc[4][4][4];
#pragma unroll
    for (int mi = 0; mi < 4; mi++)
#pragma unroll
        for (int ni = 0; ni < 4; ni++)
#pragma unroll
            for (int q = 0; q < 4; q++) acc[mi][ni][q] = 0.f;

    int lane = tid & 31, wid = tid >> 5;
    int g = lane >> 2, t4 = lane & 3;
    int wm = (wid >> 2) * 64, wn = (wid & 3) * 32;

    for (int ci = 0; ci < nch; ci++) {
        int nb = ci + 1;
        if (nb < nch) {
            int tt = nb / chPerTerm, kc = nb - tt * chPerTerm;
            int ko = kc * BKH;
            int buf = nb & 1;
            const __nv_bfloat16* Ag = Aptr[tt];
            const __nv_bfloat16* Bg = Bptr[tt];
            cp16(sA[buf] + (ra0 * ROWH + ca0) * 2, Ag + (size_t)ra0 * Kp + ko + ca0);
            cp16(sA[buf] + (ra1 * ROWH + ca1) * 2, Ag + (size_t)ra1 * Kp + ko + ca1);
            cp16(sB[buf] + (ra0 * ROWH + ca0) * 2, Bg + (size_t)ra0 * Kp + ko + ca0);
            cp16(sB[buf] + (ra1 * ROWH + ca1) * 2, Bg + (size_t)ra1 * Kp + ko + ca1);
            cp_commit();
            cp_wait1();
        } else {
            cp_wait0();
        }
        __syncthreads();

        int buf = ci & 1;
        const __nv_bfloat16* As = smA[buf];
        const __nv_bfloat16* Bs = smB[buf];
#pragma unroll
        for (int kk = 0; kk < 2; kk++) {
            int k0 = kk * 16 + 2 * t4;
            uint32_t af[4][4], bf[4][2];
#pragma unroll
            for (int mi = 0; mi < 4; mi++) {
                int r = wm + mi * 16 + g;
                const uint32_t* p = (const uint32_t*)(As + r * ROWH + k0);
                const uint32_t* p8 = (const uint32_t*)(As + (r + 8) * ROWH + k0);
                af[mi][0] = p[0]; af[mi][1] = p8[0];
                af[mi][2] = p[4]; af[mi][3] = p8[4];
            }
#pragma unroll
            for (int ni = 0; ni < 4; ni++) {
                int r = wn + ni * 8 + g;
                const uint32_t* p = (const uint32_t*)(Bs + r * ROWH + k0);
                bf[ni][0] = p[0]; bf[ni][1] = p[4];
            }
#pragma unroll
            for (int mi = 0; mi < 4; mi++)
#pragma unroll
                for (int ni = 0; ni < 4; ni++)
                    mma16816(acc[mi][ni], af[mi], bf[ni]);
        }
        __syncthreads();
    }

    // ---- epilogue ----
    if (mode == 0) {
        const float* sqb = sq + bb * NPTS;
        float* Db = Out + (size_t)bb * NPTS * NPTS;
        bool mirror = (br != bc);
#pragma unroll
        for (int mi = 0; mi < 4; mi++) {
            int n0 = rowA + wm + mi * 16 + g;
            int n1 = n0 + 8;
            float sn0 = sqb[n0], sn1 = sqb[n1];
#pragma unroll
            for (int ni = 0; ni < 4; ni++) {
                int m0 = rowB + wn + ni * 8 + 2 * t4;
#pragma unroll
                for (int h = 0; h < 2; h++) {
                    int m = m0 + h;
                    float sm_ = sqb[m];
                    float G0 = acc[mi][ni][0 + h];
                    float G1 = acc[mi][ni][2 + h];
                    float v0 = -__fadd_rn(__fadd_rn(sn0, sm_), -__fmul_rn(2.0f, G0));
                    float v1 = -__fadd_rn(__fadd_rn(sn1, sm_), -__fmul_rn(2.0f, G1));
                    Db[(size_t)n0 * NPTS + m] = v0;
                    Db[(size_t)n1 * NPTS + m] = v1;
                    if (mirror) {
                        Db[(size_t)m * NPTS + n0] = v0;
                        Db[(size_t)m * NPTS + n1] = v1;
                    }
                }
            }
        }
    } else {
        float* Ob = Out + (size_t)bb * NPTS * (size_t)JS;
#pragma unroll
        for (int mi = 0; mi < 4; mi++) {
            int n0 = rowA + wm + mi * 16 + g;
            int n1 = n0 + 8;
#pragma unroll
            for (int ni = 0; ni < 4; ni++) {
                int j0 = rowB + wn + ni * 8 + 2 * t4;
                Ob[(size_t)n0 * JS + j0]     = acc[mi][ni][0];
                Ob[(size_t)n0 * JS + j0 + 1] = acc[mi][ni][1];
                Ob[(size_t)n1 * JS + j0]     = acc[mi][ni][2];
                Ob[(size_t)n1 * JS + j0 + 1] = acc[mi][ni][3];
            }
        }
    }
}

// ---------------- approx top-8 candidates -----------------------------------
__global__ void topk8_kernel(const float* __restrict__ D, int* __restrict__ cand) {
    int b = blockIdx.y, n = blockIdx.x, tid = threadIdx.x;
    const float* row = D + ((size_t)b * NPTS + n) * NPTS;
    float tv[NCAND]; int ti[NCAND];
#pragma unroll
    for (int j = 0; j < NCAND; j++) { tv[j] = -__int_as_float(0x7f800000); ti[j] = 0x7fffffff; }
    for (int m = tid; m < NPTS; m += 256) {
        float v = row[m];
        if (v > tv[NCAND - 1]) {
            int j = NCAND - 1;
            while (j > 0 && v > tv[j - 1]) { tv[j] = tv[j - 1]; ti[j] = ti[j - 1]; j--; }
            tv[j] = v; ti[j] = m;
        }
    }
    __shared__ float sv[256];
    __shared__ int   si[256];
    __shared__ int   swin;
    int head = 0;
    for (int p = 0; p < NCAND; p++) {
        sv[tid] = (head < NCAND) ? tv[head] : -__int_as_float(0x7f800000);
        si[tid] = (head < NCAND) ? ti[head] : 0x7fffffff;
        __syncthreads();
        if (tid < 32) {
            float bv = -__int_as_float(0x7f800000);
            int bi = 0x7fffffff, bt = -1;
            for (int t = tid; t < 256; t += 32) {
                float v = sv[t]; int i2 = si[t];
                if (v > bv || (v == bv && i2 < bi)) { bv = v; bi = i2; bt = t; }
            }
            for (int off = 16; off; off >>= 1) {
                float ov = __shfl_down_sync(0xffffffffu, bv, off);
                int oi = __shfl_down_sync(0xffffffffu, bi, off);
                int ot = __shfl_down_sync(0xffffffffu, bt, off);
                if (ov > bv || (ov == bv && oi < bi)) { bv = ov; bi = oi; bt = ot; }
            }
            if (tid == 0) { cand[((size_t)b * NPTS + n) * NCAND + p] = bi; swin = bt; }
        }
        __syncthreads();
        if (tid == swin) head++;
        __syncthreads();
    }
}

// ---------------- exact rescore of 8 candidates -> top-5 ---------------------
__global__ void rescore_kernel(const float* __restrict__ X, const float* __restrict__ sq,
                               const int* __restrict__ cand, int* __restrict__ idx, int Cdim) {
    int b = blockIdx.y, n = blockIdx.x, tid = threadIdx.x;
    __shared__ float xn[896];
    __shared__ double red[4];
    __shared__ float vals[NCAND];
    __shared__ int   vm[NCAND];
    const float* xrow = X + ((size_t)b * NPTS + n) * Cdim;
    for (int c = tid; c < Cdim; c += 128) xn[c] = xrow[c];
    __syncthreads();
    const float* sqb = sq + b * NPTS;
    float sn = sqb[n];
    for (int j = 0; j < NCAND; j++) {
        int m = cand[((size_t)b * NPTS + n) * NCAND + j];
        const float* xm = X + ((size_t)b * NPTS + m) * Cdim;
        double s = 0.0;
        for (int c = tid; c < Cdim; c += 128) s += (double)xn[c] * (double)xm[c];
        for (int off = 16; off; off >>= 1) s += __shfl_down_sync(0xffffffffu, s, off);
        if ((tid & 31) == 0) red[tid >> 5] = s;
        __syncthreads();
        if (tid == 0) {
            float Gf = (float)(red[0] + red[1] + red[2] + red[3]);
            float t1 = __fadd_rn(sn, sqb[m]);
            vals[j] = -__fadd_rn(t1, -__fmul_rn(2.0f, Gf));
            vm[j] = m;
        }
        __syncthreads();
    }
    if (tid == 0) {
        bool used[NCAND] = {};
        for (int p = 0; p < KNN; p++) {
            float bv = -__int_as_float(0x7f800000); int bi = 0x7fffffff, bj = -1;
            for (int j = 0; j < NCAND; j++) {
                if (used[j]) continue;
                if (vals[j] > bv || (vals[j] == bv && vm[j] < bi)) { bv = vals[j]; bi = vm[j]; bj = j; }
            }
            used[bj] = true;
            idx[((size_t)b * NPTS + n) * KNN + p] = bi;
        }
    }
}

// ---------------- gather + max over k + BN + LeakyReLU -----------------------
__global__ void gathermax_kernel(const float* __restrict__ PQ, const int* __restrict__ idx,
                                 const float* __restrict__ gamma, const float* __restrict__ beta,
                                 const float* __restrict__ mean, const float* __restrict__ var,
                                 float* __restrict__ out, int OUT, int JS) {
    int b = blockIdx.y, n = blockIdx.x;
    __shared__ int nb[KNN];
    if (threadIdx.x < KNN) nb[threadIdx.x] = idx[((size_t)b * NPTS + n) * KNN + threadIdx.x];
    __syncthreads();
    const float* base = PQ + (size_t)b * NPTS * JS;
    const float* p0 = base + (size_t)nb[0] * JS;
    const float* p1 = base + (size_t)nb[1] * JS;
    const float* p2 = base + (size_t)nb[2] * JS;
    const float* p3 = base + (size_t)nb[3] * JS;
    const float* p4 = base + (size_t)nb[4] * JS;
    const float* q  = base + (size_t)n * JS + OUT;
    float* orow = out + ((size_t)b * NPTS + n) * OUT;
    for (int o = threadIdx.x; o < OUT; o += blockDim.x) {
        float m = p0[o];
        m = fmaxf(m, p1[o]); m = fmaxf(m, p2[o]); m = fmaxf(m, p3[o]); m = fmaxf(m, p4[o]);
        double h = (double)m + (double)q[o];
        double s = (double)gamma[o] * rsqrt((double)var[o] + 1e-5);
        double v = (h - (double)mean[o]) * s + (double)beta[o];
        float vf = (float)v;
        orow[o] = (vf >= 0.f) ? vf : 0.2f * vf;
    }
}

// ---------------- launcher ---------------------------------------------------
extern "C" void kernel_launch(void* const* d_in, const int* in_sizes, int n_in,
                              void* d_out, int out_size) {
    const float* X0 = (const float*)d_in[0];
    const float* W1 = (const float*)d_in[1];
    const float* g1 = (const float*)d_in[2];
    const float* b1 = (const float*)d_in[3];
    const float* m1 = (const float*)d_in[4];
    const float* v1 = (const float*)d_in[5];
    const float* W2 = (const float*)d_in[6];
    const float* g2 = (const float*)d_in[7];
    const float* b2 = (const float*)d_in[8];
    const float* m2 = (const float*)d_in[9];
    const float* v2 = (const float*)d_in[10];
    float* out = (float*)d_out;

    float *pD, *pPQ, *pX1, *pSq;
    __nv_bfloat16 *pXA, *pWB;
    int *pIdx, *pCand;
    cudaGetSymbolAddress((void**)&pD, g_D);
    cudaGetSymbolAddress((void**)&pPQ, g_PQ);
    cudaGetSymbolAddress((void**)&pX1, g_X1);
    cudaGetSymbolAddress((void**)&pXA, g_XA);
    cudaGetSymbolAddress((void**)&pWB, g_WB);
    cudaGetSymbolAddress((void**)&pSq, g_sq);
    cudaGetSymbolAddress((void**)&pIdx, g_idx);
    cudaGetSymbolAddress((void**)&pCand, g_cand);

    TermList T1; T1.n = 1;
    T1.pa[0] = 0; T1.pb[0] = 0; T1.pa[1] = T1.pa[2] = 0; T1.pb[1] = T1.pb[2] = 0;
    TermList T3; T3.n = 3;
    T3.pa[0] = 0; T3.pb[0] = 0;
    T3.pa[1] = 0; T3.pb[1] = 1;
    T3.pa[2] = 1; T3.pb[2] = 0;

    size_t aPlane1 = (size_t)BATCH * NPTS * KP1;
    size_t aPlane2 = (size_t)BATCH * NPTS * KP2;
    size_t wPlane  = (size_t)J2P * KP2;   // shared plane stride for both layers

    // ---- Layer 1 (Cin=512, OUT=864, JS=1792) ----
    rowsq_kernel<<<dim3(NPTS, BATCH), 128>>>(X0, pSq, C1);
    split3x_kernel<<<4096, 256>>>(X0, pXA, C1, KP1, aPlane1);
    splitW_kernel<<<2048, 256>>>(W1, pWB, C1, H1, KP1, wPlane);
    hmma_gemm_kernel<<<dim3(32, 32, BATCH), 256>>>(
        pXA, pXA, aPlane1, aPlane1, (size_t)NPTS * KP1, (size_t)NPTS * KP1,
        KP1, T1, 0, pSq, pD, NPTS);
    topk8_kernel<<<dim3(NPTS, BATCH), 256>>>(pD, pCand);
    rescore_kernel<<<dim3(NPTS, BATCH), 128>>>(X0, pSq, pCand, pIdx, C1);
    hmma_gemm_kernel<<<dim3(J1P / BN, 32, BATCH), 256>>>(
        pXA, pWB, aPlane1, wPlane, (size_t)NPTS * KP1, 0,
        KP1, T3, 1, pSq, pPQ, J1P);
    gathermax_kernel<<<dim3(NPTS, BATCH), 256>>>(pPQ, pIdx, g1, b1, m1, v1, pX1, H1, J1P);

    // ---- Layer 2 (Cin=864 pad 896, OUT=1728, JS=3456) ----
    rowsq_kernel<<<dim3(NPTS, BATCH), 128>>>(pX1, pSq, H1);
    split3x_kernel<<<4096, 256>>>(pX1, pXA, H1, KP2, aPlane2);
    splitW_kernel<<<4096, 256>>>(W2, pWB, H1, H2, KP2, wPlane);
    hmma_gemm_kernel<<<dim3(32, 32, BATCH), 256>>>(
        pXA, pXA, aPlane2, aPlane2, (size_t)NPTS * KP2, (size_t)NPTS * KP2,
        KP2, T1, 0, pSq, pD, NPTS);
    topk8_kernel<<<dim3(NPTS, BATCH), 256>>>(pD, pCand);
    rescore_kernel<<<dim3(NPTS, BATCH), 128>>>(pX1, pSq, pCand, pIdx, H1);
    hmma_gemm_kernel<<<dim3(J2P / BN, 32, BATCH), 256>>>(
        pXA, pWB, aPlane2, wPlane, (size_t)NPTS * KP2, 0,
        KP2, T3, 1, pSq, pPQ, J2P);
    gathermax_kernel<<<dim3(NPTS, BATCH), 256>>>(pPQ, pIdx, g2, b2, m2, v2, out, H2, J2P);
}